// round 13
// baseline (speedup 1.0000x reference)
#include <cuda_runtime.h>
#include <cuda_fp16.h>
#include <cstdint>

#define MARGIN   0.1f
#define BEPS     1e-5f
#define LN2      0.69314718056f
#define INV_LN2  1.44269504089f

#define MAXB 4608
#define MAXC 10240

static __device__ double       g_hsum;
static __device__ unsigned int g_count;
static __device__ float4  g_rowp[MAXB];        // (pn*cb, cb, sc2, 0)
static __device__ float2  g_colp[MAXC];        // (ca, an*ca)  [pad: (0, 3e4)]
static __device__ __half  g_As[MAXB * 64];     // fp16(-2*cb*pred), row-swizzled (128B rows)
static __device__ __half  g_Bs[MAXC * 64];     // fp16(ca*all),     row-swizzled

// ---------------- helpers ----------------
__device__ __forceinline__ uint32_t smem_u32(const void* p) {
    uint32_t a;
    asm("{ .reg .u64 t; cvta.to.shared.u64 t, %1; cvt.u32.u64 %0, t; }" : "=r"(a) : "l"(p));
    return a;
}
__device__ __forceinline__ uint32_t h2(float a, float b) {
    __half2 v = __floats2half2_rn(a, b);
    return *(uint32_t*)&v;
}
__device__ __forceinline__ void ldm_x4(uint32_t* r, uint32_t addr) {
    asm volatile("ldmatrix.sync.aligned.m8n8.x4.shared.b16 {%0,%1,%2,%3}, [%4];"
                 : "=r"(r[0]), "=r"(r[1]), "=r"(r[2]), "=r"(r[3]) : "r"(addr));
}
__device__ __forceinline__ void mma_f16(float* c, const uint32_t* a,
                                        uint32_t b0, uint32_t b1) {
    asm volatile(
        "mma.sync.aligned.m16n8k16.row.col.f32.f16.f16.f32 "
        "{%0,%1,%2,%3}, {%4,%5,%6,%7}, {%8,%9}, {%0,%1,%2,%3};"
        : "+f"(c[0]), "+f"(c[1]), "+f"(c[2]), "+f"(c[3])
        : "r"(a[0]), "r"(a[1]), "r"(a[2]), "r"(a[3]), "r"(b0), "r"(b1));
}
__device__ __forceinline__ void cp_async16(uint32_t smem_addr, const void* gmem) {
    asm volatile("cp.async.cg.shared.global [%0], [%1], 16;"
                 :: "r"(smem_addr), "l"(gmem) : "memory");
}

// ---------------- prep ----------------
__global__ void prep_kernel(const float* __restrict__ pred,
                            const float* __restrict__ tgt,
                            const float* __restrict__ all,
                            int B, int C, int Bp, int Cp) {
    int gid  = blockIdx.x * blockDim.x + threadIdx.x;
    if (gid == 0) { g_hsum = 0.0; g_count = 0u; }
    int r    = gid >> 3;
    int lane = gid & 7;

    if (r < Cp) {
        char* dst = (char*)g_Bs + (size_t)r * 128;
        uint32_t so = (uint32_t)((lane ^ (r & 7)) << 4);
        if (r < C) {
            float4 a0 = ((const float4*)(all + (size_t)r * 64))[lane * 2];
            float4 a1 = ((const float4*)(all + (size_t)r * 64))[lane * 2 + 1];
            float s = 0.f;
            s = fmaf(a0.x, a0.x, s); s = fmaf(a0.y, a0.y, s);
            s = fmaf(a0.z, a0.z, s); s = fmaf(a0.w, a0.w, s);
            s = fmaf(a1.x, a1.x, s); s = fmaf(a1.y, a1.y, s);
            s = fmaf(a1.z, a1.z, s); s = fmaf(a1.w, a1.w, s);
            s += __shfl_xor_sync(0xFFFFFFFFu, s, 1);
            s += __shfl_xor_sync(0xFFFFFFFFu, s, 2);
            s += __shfl_xor_sync(0xFFFFFFFFu, s, 4);
            float an = fminf(fmaxf(s, 0.f), 1.0f - BEPS);
            float ca = 1.0f / (1.0f - an);
            *(uint4*)(dst + so) = make_uint4(
                h2(ca*a0.x, ca*a0.y), h2(ca*a0.z, ca*a0.w),
                h2(ca*a1.x, ca*a1.y), h2(ca*a1.z, ca*a1.w));
            if (lane == 0) g_colp[r] = make_float2(ca, an * ca);
        } else {
            *(uint4*)(dst + so) = make_uint4(0u, 0u, 0u, 0u);
            if (lane == 0) g_colp[r] = make_float2(0.f, 3e4f);
        }
    }

    if (r < Bp) {
        char* dst = (char*)g_As + (size_t)r * 128;
        uint32_t so = (uint32_t)((lane ^ (r & 7)) << 4);
        if (r < B) {
            float4 p0 = ((const float4*)(pred + (size_t)r * 64))[lane * 2];
            float4 p1 = ((const float4*)(pred + (size_t)r * 64))[lane * 2 + 1];
            float4 t0 = ((const float4*)(tgt  + (size_t)r * 64))[lane * 2];
            float4 t1 = ((const float4*)(tgt  + (size_t)r * 64))[lane * 2 + 1];
            float pn = 0.f, tn = 0.f, sq = 0.f;
            pn = fmaf(p0.x,p0.x,pn); pn = fmaf(p0.y,p0.y,pn); pn = fmaf(p0.z,p0.z,pn); pn = fmaf(p0.w,p0.w,pn);
            pn = fmaf(p1.x,p1.x,pn); pn = fmaf(p1.y,p1.y,pn); pn = fmaf(p1.z,p1.z,pn); pn = fmaf(p1.w,p1.w,pn);
            tn = fmaf(t0.x,t0.x,tn); tn = fmaf(t0.y,t0.y,tn); tn = fmaf(t0.z,t0.z,tn); tn = fmaf(t0.w,t0.w,tn);
            tn = fmaf(t1.x,t1.x,tn); tn = fmaf(t1.y,t1.y,tn); tn = fmaf(t1.z,t1.z,tn); tn = fmaf(t1.w,t1.w,tn);
            float dx;
            dx = p0.x-t0.x; sq = fmaf(dx,dx,sq); dx = p0.y-t0.y; sq = fmaf(dx,dx,sq);
            dx = p0.z-t0.z; sq = fmaf(dx,dx,sq); dx = p0.w-t0.w; sq = fmaf(dx,dx,sq);
            dx = p1.x-t1.x; sq = fmaf(dx,dx,sq); dx = p1.y-t1.y; sq = fmaf(dx,dx,sq);
            dx = p1.z-t1.z; sq = fmaf(dx,dx,sq); dx = p1.w-t1.w; sq = fmaf(dx,dx,sq);
            pn += __shfl_xor_sync(0xFFFFFFFFu, pn, 1);
            pn += __shfl_xor_sync(0xFFFFFFFFu, pn, 2);
            pn += __shfl_xor_sync(0xFFFFFFFFu, pn, 4);
            tn += __shfl_xor_sync(0xFFFFFFFFu, tn, 1);
            tn += __shfl_xor_sync(0xFFFFFFFFu, tn, 2);
            tn += __shfl_xor_sync(0xFFFFFFFFu, tn, 4);
            sq += __shfl_xor_sync(0xFFFFFFFFu, sq, 1);
            sq += __shfl_xor_sync(0xFFFFFFFFu, sq, 2);
            sq += __shfl_xor_sync(0xFFFFFFFFu, sq, 4);
            pn = fminf(fmaxf(pn, 0.f), 1.0f - BEPS);
            tn = fminf(fmaxf(tn, 0.f), 1.0f - BEPS);
            float cb = 2.0f / (1.0f - pn);
            float m2cb = -2.0f * cb;
            *(uint4*)(dst + so) = make_uint4(
                h2(m2cb*p0.x, m2cb*p0.y), h2(m2cb*p0.z, m2cb*p0.w),
                h2(m2cb*p1.x, m2cb*p1.y), h2(m2cb*p1.z, m2cb*p1.w));
            if (lane == 0) {
                float x = 1.0f + 2.0f * sq / ((1.0f - pn) * (1.0f - tn));
                x = fmaxf(x, 1.0f + 1e-7f);
                float d2c = logf(x + sqrtf(x * x - 1.0f));
                g_rowp[r] = make_float4(pn * cb, cb, (d2c + MARGIN) * INV_LN2, 0.f);
            }
        } else {
            *(uint4*)(dst + so) = make_uint4(0u, 0u, 0u, 0u);
            if (lane == 0) g_rowp[r] = make_float4(0.f, 0.f, 0.f, 0.f);
        }
    }
}

// ---------------- main: interleaved MMA + epilogue per 16-col block ----------------
#define BM 128
#define BN 128
#define OFF_A    0
#define OFF_B    16384
#define OFF_CP   32768
#define OFF_RED  33792
#define SMEM_SZ  33856

__global__ __launch_bounds__(256, 2)
void poincare_mma_kernel(float* __restrict__ out, int B, int C, unsigned int nblocks) {
    extern __shared__ char smem[];
    const uint32_t sbase = smem_u32(smem);
    const int tid  = threadIdx.x;
    const int w    = tid >> 5;
    const int lane = tid & 31;
    const int bm   = blockIdx.y * BM;
    const int bn   = blockIdx.x * BN;
    const int wm   = w & 3;
    const int wn   = w >> 2;

    // ---- async tile copy ----
    {
        const char* srcA = (const char*)g_As + (size_t)bm * 128;
        const char* srcB = (const char*)g_Bs + (size_t)bn * 128;
#pragma unroll
        for (int i = 0; i < 4; i++) {
            int idx = tid + i * 256;
            cp_async16(sbase + OFF_A + (idx << 4), srcA + (idx << 4));
            cp_async16(sbase + OFF_B + (idx << 4), srcB + (idx << 4));
        }
        asm volatile("cp.async.commit_group;" ::: "memory");
    }
    if (tid < 128) {
        float2 cpv = g_colp[bn + tid];
        ((float2*)(smem + OFF_CP))[tid] = cpv;
    }
    asm volatile("cp.async.wait_group 0;" ::: "memory");
    __syncthreads();

    // ---- fragment addressing ----
    const int rsel = lane & 15;
    const int csel = lane >> 4;
    const int rowA = wm * 32 + rsel;
    const int swA  = rowA & 7;
    const uint32_t baseA = sbase + OFF_A + (uint32_t)(rowA << 7);
    const int rB   = wn * 64 + rsel;     // + jp*16 below
    const int swB  = rB & 7;
    const uint32_t baseB = sbase + OFF_B + (uint32_t)(rB << 7);

    // ---- preload all A fragments (reused for every jp) ----
    uint32_t af[4][2][4];
#pragma unroll
    for (int s = 0; s < 4; s++)
#pragma unroll
        for (int i = 0; i < 2; i++)
            ldm_x4(af[s][i], baseA + (uint32_t)(i * 16 * 128)
                          + (uint32_t)((((2 * s + csel) ^ swA) << 4)));

    // ---- row params + extras A fragment ----
    float4 rp[4];
#pragma unroll
    for (int t = 0; t < 4; t++)
        rp[t] = g_rowp[bm + wm * 32 + (lane >> 2) + t * 8];

    const bool k0lane = (lane & 3) == 0;
    uint32_t aex[2][4];
#pragma unroll
    for (int i = 0; i < 2; i++) {
        aex[i][0] = k0lane ? h2(rp[2 * i].x,     rp[2 * i].y)     : 0u;
        aex[i][1] = k0lane ? h2(rp[2 * i + 1].x, rp[2 * i + 1].y) : 0u;
        aex[i][2] = 0u;
        aex[i][3] = 0u;
    }
    const float2* cp = (const float2*)(smem + OFF_CP);

    // ---- per-jp: MMA burst then epilogue burst (pipes overlap across warps) ----
    float hs = 0.f;
#pragma unroll
    for (int jp = 0; jp < 4; jp++) {
        float acc[2][2][4];
#pragma unroll
        for (int i = 0; i < 2; i++)
#pragma unroll
            for (int t = 0; t < 2; t++)
#pragma unroll
                for (int q = 0; q < 4; q++) acc[i][t][q] = 0.f;

#pragma unroll
        for (int s = 0; s < 4; s++) {
            uint32_t bf[4];
            ldm_x4(bf, baseB + (uint32_t)(jp * 16 * 128)
                     + (uint32_t)((((2 * s + csel) ^ swB) << 4)));
#pragma unroll
            for (int i = 0; i < 2; i++) {
                mma_f16(acc[i][0], af[s][i], bf[0], bf[2]);
                mma_f16(acc[i][1], af[s][i], bf[1], bf[3]);
            }
        }
        // extras k-step
        uint32_t bex[2];
#pragma unroll
        for (int t = 0; t < 2; t++) {
            float2 cc = cp[wn * 64 + (jp * 2 + t) * 8 + (lane >> 2)];
            bex[t] = k0lane ? h2(cc.x, cc.y) : 0u;
        }
#pragma unroll
        for (int i = 0; i < 2; i++)
#pragma unroll
            for (int t = 0; t < 2; t++)
                mma_f16(acc[i][t], aex[i], bex[t], 0u);

        // epilogue on these 16 columns
#pragma unroll
        for (int i = 0; i < 2; i++) {
#pragma unroll
            for (int t = 0; t < 2; t++) {
#pragma unroll
                for (int h = 0; h < 2; h++) {
                    float sc2 = rp[2 * i + h].z;
#pragma unroll
                    for (int q = 0; q < 2; q++) {
                        float e  = acc[i][t][h * 2 + q];
                        float g  = fmaxf(e, 0.f);
                        float tq = g * (g + 2.0f);
                        float st;  asm("sqrt.approx.f32 %0, %1;" : "=f"(st) : "f"(tq));
                        float arg = (g + 1.0f) + st;
                        float lg;  asm("lg2.approx.f32 %0, %1;" : "=f"(lg) : "f"(arg));
                        hs += fmaxf(sc2 - lg, 0.f);
                    }
                }
            }
        }
    }

    // ---- reduce + fused finalize ----
#pragma unroll
    for (int s = 16; s > 0; s >>= 1)
        hs += __shfl_xor_sync(0xFFFFFFFFu, hs, s);
    if (lane == 0) ((float*)(smem + OFF_RED))[w] = hs;
    __syncthreads();
    if (w == 0) {
        float v = (lane < 8) ? ((float*)(smem + OFF_RED))[lane] : 0.f;
#pragma unroll
        for (int s = 4; s > 0; s >>= 1)
            v += __shfl_xor_sync(0xFFFFFFFFu, v, s);
        if (lane == 0) {
            atomicAdd(&g_hsum, (double)(v * LN2));
            __threadfence();
            unsigned int ticket = atomicAdd(&g_count, 1u);
            if (ticket == nblocks - 1u) {
                double h = g_hsum;
                out[0] = (float)((h - 0.1 * (double)B) / (double)B);
            }
        }
    }
}

extern "C" void kernel_launch(void* const* d_in, const int* in_sizes, int n_in,
                              void* d_out, int out_size) {
    const float* pred = (const float*)d_in[0];
    const float* tgt  = (const float*)d_in[1];
    const float* all  = (const float*)d_in[2];
    float* out = (float*)d_out;

    int B = in_sizes[0] / 64;
    int C = in_sizes[2] / 64;
    int Bp = ((B + 127) / 128) * 128;
    int Cp = ((C + 127) / 128) * 128;

    cudaFuncSetAttribute(poincare_mma_kernel,
                         cudaFuncAttributeMaxDynamicSharedMemorySize, SMEM_SZ);

    int nthr = ((Bp > Cp) ? Bp : Cp) * 8;
    prep_kernel<<<(nthr + 255) / 256, 256>>>(pred, tgt, all, B, C, Bp, Cp);

    dim3 grid(Cp / BN, Bp / BM);
    unsigned int nblocks = grid.x * grid.y;
    poincare_mma_kernel<<<grid, 256, SMEM_SZ>>>(out, B, C, nblocks);
}

// round 15
// speedup vs baseline: 1.0210x; 1.0210x over previous
#include <cuda_runtime.h>
#include <cuda_fp16.h>
#include <cstdint>

#define MARGIN   0.1f
#define BEPS     1e-5f
#define LN2      0.69314718056f
#define INV_LN2  1.44269504089f

#define MAXB 4608
#define MAXC 10240

static __device__ double       g_hsum;
static __device__ unsigned int g_count;
static __device__ float4  g_rowp[MAXB];        // (pn*cb, cb, sc2, 0)
static __device__ float2  g_colp[MAXC];        // (ca, an*ca)  [pad: (0, 3e4)]
static __device__ __half  g_As[MAXB * 64];     // fp16(-2*cb*pred), row-swizzled (128B rows)
static __device__ __half  g_Bs[MAXC * 64];     // fp16(ca*all),     row-swizzled

// ---------------- helpers ----------------
__device__ __forceinline__ uint32_t smem_u32(const void* p) {
    uint32_t a;
    asm("{ .reg .u64 t; cvta.to.shared.u64 t, %1; cvt.u32.u64 %0, t; }" : "=r"(a) : "l"(p));
    return a;
}
__device__ __forceinline__ uint32_t h2(float a, float b) {
    __half2 v = __floats2half2_rn(a, b);
    return *(uint32_t*)&v;
}
__device__ __forceinline__ void ldm_x4(uint32_t* r, uint32_t addr) {
    asm volatile("ldmatrix.sync.aligned.m8n8.x4.shared.b16 {%0,%1,%2,%3}, [%4];"
                 : "=r"(r[0]), "=r"(r[1]), "=r"(r[2]), "=r"(r[3]) : "r"(addr));
}
__device__ __forceinline__ void mma_f16(float* c, const uint32_t* a,
                                        uint32_t b0, uint32_t b1) {
    asm volatile(
        "mma.sync.aligned.m16n8k16.row.col.f32.f16.f16.f32 "
        "{%0,%1,%2,%3}, {%4,%5,%6,%7}, {%8,%9}, {%0,%1,%2,%3};"
        : "+f"(c[0]), "+f"(c[1]), "+f"(c[2]), "+f"(c[3])
        : "r"(a[0]), "r"(a[1]), "r"(a[2]), "r"(a[3]), "r"(b0), "r"(b1));
}
__device__ __forceinline__ void cp_async16(uint32_t smem_addr, const void* gmem) {
    asm volatile("cp.async.cg.shared.global [%0], [%1], 16;"
                 :: "r"(smem_addr), "l"(gmem) : "memory");
}

// ---------------- prep ----------------
__global__ void prep_kernel(const float* __restrict__ pred,
                            const float* __restrict__ tgt,
                            const float* __restrict__ all,
                            int B, int C, int Bp, int Cp) {
    int gid  = blockIdx.x * blockDim.x + threadIdx.x;
    if (gid == 0) { g_hsum = 0.0; g_count = 0u; }
    int r    = gid >> 3;
    int lane = gid & 7;

    if (r < Cp) {
        char* dst = (char*)g_Bs + (size_t)r * 128;
        uint32_t so = (uint32_t)((lane ^ (r & 7)) << 4);
        if (r < C) {
            float4 a0 = ((const float4*)(all + (size_t)r * 64))[lane * 2];
            float4 a1 = ((const float4*)(all + (size_t)r * 64))[lane * 2 + 1];
            float s = 0.f;
            s = fmaf(a0.x, a0.x, s); s = fmaf(a0.y, a0.y, s);
            s = fmaf(a0.z, a0.z, s); s = fmaf(a0.w, a0.w, s);
            s = fmaf(a1.x, a1.x, s); s = fmaf(a1.y, a1.y, s);
            s = fmaf(a1.z, a1.z, s); s = fmaf(a1.w, a1.w, s);
            s += __shfl_xor_sync(0xFFFFFFFFu, s, 1);
            s += __shfl_xor_sync(0xFFFFFFFFu, s, 2);
            s += __shfl_xor_sync(0xFFFFFFFFu, s, 4);
            float an = fminf(fmaxf(s, 0.f), 1.0f - BEPS);
            float ca = 1.0f / (1.0f - an);
            *(uint4*)(dst + so) = make_uint4(
                h2(ca*a0.x, ca*a0.y), h2(ca*a0.z, ca*a0.w),
                h2(ca*a1.x, ca*a1.y), h2(ca*a1.z, ca*a1.w));
            if (lane == 0) g_colp[r] = make_float2(ca, an * ca);
        } else {
            *(uint4*)(dst + so) = make_uint4(0u, 0u, 0u, 0u);
            if (lane == 0) g_colp[r] = make_float2(0.f, 3e4f);
        }
    }

    if (r < Bp) {
        char* dst = (char*)g_As + (size_t)r * 128;
        uint32_t so = (uint32_t)((lane ^ (r & 7)) << 4);
        if (r < B) {
            float4 p0 = ((const float4*)(pred + (size_t)r * 64))[lane * 2];
            float4 p1 = ((const float4*)(pred + (size_t)r * 64))[lane * 2 + 1];
            float4 t0 = ((const float4*)(tgt  + (size_t)r * 64))[lane * 2];
            float4 t1 = ((const float4*)(tgt  + (size_t)r * 64))[lane * 2 + 1];
            float pn = 0.f, tn = 0.f, sq = 0.f;
            pn = fmaf(p0.x,p0.x,pn); pn = fmaf(p0.y,p0.y,pn); pn = fmaf(p0.z,p0.z,pn); pn = fmaf(p0.w,p0.w,pn);
            pn = fmaf(p1.x,p1.x,pn); pn = fmaf(p1.y,p1.y,pn); pn = fmaf(p1.z,p1.z,pn); pn = fmaf(p1.w,p1.w,pn);
            tn = fmaf(t0.x,t0.x,tn); tn = fmaf(t0.y,t0.y,tn); tn = fmaf(t0.z,t0.z,tn); tn = fmaf(t0.w,t0.w,tn);
            tn = fmaf(t1.x,t1.x,tn); tn = fmaf(t1.y,t1.y,tn); tn = fmaf(t1.z,t1.z,tn); tn = fmaf(t1.w,t1.w,tn);
            float dx;
            dx = p0.x-t0.x; sq = fmaf(dx,dx,sq); dx = p0.y-t0.y; sq = fmaf(dx,dx,sq);
            dx = p0.z-t0.z; sq = fmaf(dx,dx,sq); dx = p0.w-t0.w; sq = fmaf(dx,dx,sq);
            dx = p1.x-t1.x; sq = fmaf(dx,dx,sq); dx = p1.y-t1.y; sq = fmaf(dx,dx,sq);
            dx = p1.z-t1.z; sq = fmaf(dx,dx,sq); dx = p1.w-t1.w; sq = fmaf(dx,dx,sq);
            pn += __shfl_xor_sync(0xFFFFFFFFu, pn, 1);
            pn += __shfl_xor_sync(0xFFFFFFFFu, pn, 2);
            pn += __shfl_xor_sync(0xFFFFFFFFu, pn, 4);
            tn += __shfl_xor_sync(0xFFFFFFFFu, tn, 1);
            tn += __shfl_xor_sync(0xFFFFFFFFu, tn, 2);
            tn += __shfl_xor_sync(0xFFFFFFFFu, tn, 4);
            sq += __shfl_xor_sync(0xFFFFFFFFu, sq, 1);
            sq += __shfl_xor_sync(0xFFFFFFFFu, sq, 2);
            sq += __shfl_xor_sync(0xFFFFFFFFu, sq, 4);
            pn = fminf(fmaxf(pn, 0.f), 1.0f - BEPS);
            tn = fminf(fmaxf(tn, 0.f), 1.0f - BEPS);
            float cb = 2.0f / (1.0f - pn);
            float m2cb = -2.0f * cb;
            *(uint4*)(dst + so) = make_uint4(
                h2(m2cb*p0.x, m2cb*p0.y), h2(m2cb*p0.z, m2cb*p0.w),
                h2(m2cb*p1.x, m2cb*p1.y), h2(m2cb*p1.z, m2cb*p1.w));
            if (lane == 0) {
                float x = 1.0f + 2.0f * sq / ((1.0f - pn) * (1.0f - tn));
                x = fmaxf(x, 1.0f + 1e-7f);
                float d2c = logf(x + sqrtf(x * x - 1.0f));
                g_rowp[r] = make_float4(pn * cb, cb, (d2c + MARGIN) * INV_LN2, 0.f);
            }
        } else {
            *(uint4*)(dst + so) = make_uint4(0u, 0u, 0u, 0u);
            if (lane == 0) g_rowp[r] = make_float4(0.f, 0.f, 0.f, 0.f);
        }
    }
}

// ---------------- main: 3 CTAs/SM, A-frags reloaded, slim epilogue ----------------
#define BM 128
#define BN 128
#define OFF_A    0
#define OFF_B    16384
#define OFF_CP   32768
#define OFF_RED  33792
#define SMEM_SZ  33856

__global__ __launch_bounds__(256, 3)
void poincare_mma_kernel(float* __restrict__ out, int B, int C, unsigned int nblocks) {
    extern __shared__ char smem[];
    const uint32_t sbase = smem_u32(smem);
    const int tid  = threadIdx.x;
    const int w    = tid >> 5;
    const int lane = tid & 31;
    const int bm   = blockIdx.y * BM;
    const int bn   = blockIdx.x * BN;
    const int wm   = w & 3;
    const int wn   = w >> 2;

    // ---- async tile copy ----
    {
        const char* srcA = (const char*)g_As + (size_t)bm * 128;
        const char* srcB = (const char*)g_Bs + (size_t)bn * 128;
#pragma unroll
        for (int i = 0; i < 4; i++) {
            int idx = tid + i * 256;
            cp_async16(sbase + OFF_A + (idx << 4), srcA + (idx << 4));
            cp_async16(sbase + OFF_B + (idx << 4), srcB + (idx << 4));
        }
        asm volatile("cp.async.commit_group;" ::: "memory");
    }
    if (tid < 128) {
        float2 cpv = g_colp[bn + tid];
        ((float2*)(smem + OFF_CP))[tid] = cpv;
    }
    asm volatile("cp.async.wait_group 0;" ::: "memory");
    __syncthreads();

    // ---- fragment addressing ----
    const int rsel = lane & 15;
    const int csel = lane >> 4;
    const int rowA = wm * 32 + rsel;
    const int swA  = rowA & 7;
    const uint32_t baseA = sbase + OFF_A + (uint32_t)(rowA << 7);
    const int rB   = wn * 64 + rsel;     // + jp*16 below
    const int swB  = rB & 7;
    const uint32_t baseB = sbase + OFF_B + (uint32_t)(rB << 7);

    // ---- row params: consume rp into aex + sc2 (small live set) ----
    float sc2[4];
    uint32_t aex[2][4];
    {
        const bool k0 = (lane & 3) == 0;
        int rbase = bm + wm * 32 + (lane >> 2);
        float4 r0 = g_rowp[rbase];
        float4 r1 = g_rowp[rbase + 8];
        float4 r2 = g_rowp[rbase + 16];
        float4 r3 = g_rowp[rbase + 24];
        sc2[0] = r0.z; sc2[1] = r1.z; sc2[2] = r2.z; sc2[3] = r3.z;
        aex[0][0] = k0 ? h2(r0.x, r0.y) : 0u;
        aex[0][1] = k0 ? h2(r1.x, r1.y) : 0u;
        aex[0][2] = 0u; aex[0][3] = 0u;
        aex[1][0] = k0 ? h2(r2.x, r2.y) : 0u;
        aex[1][1] = k0 ? h2(r3.x, r3.y) : 0u;
        aex[1][2] = 0u; aex[1][3] = 0u;
    }
    const bool k0lane = (lane & 3) == 0;
    const float2* cp = (const float2*)(smem + OFF_CP);

    // ---- per-jp: load frags, MMA, epilogue (A reloaded each jp to cut regs) ----
    float hs = 0.f;
#pragma unroll
    for (int jp = 0; jp < 4; jp++) {
        float acc[2][2][4];
#pragma unroll
        for (int i = 0; i < 2; i++)
#pragma unroll
            for (int t = 0; t < 2; t++)
#pragma unroll
                for (int q = 0; q < 4; q++) acc[i][t][q] = 0.f;

#pragma unroll
        for (int s = 0; s < 4; s++) {
            uint32_t af0[4], af1[4], bf[4];
            uint32_t koff = (uint32_t)((2 * s + csel));
            ldm_x4(af0, baseA + (uint32_t)(((koff ^ swA) << 4)));
            ldm_x4(af1, baseA + (uint32_t)(16 * 128) + (uint32_t)(((koff ^ swA) << 4)));
            ldm_x4(bf,  baseB + (uint32_t)(jp * 16 * 128) + (uint32_t)(((koff ^ swB) << 4)));
            mma_f16(acc[0][0], af0, bf[0], bf[2]);
            mma_f16(acc[0][1], af0, bf[1], bf[3]);
            mma_f16(acc[1][0], af1, bf[0], bf[2]);
            mma_f16(acc[1][1], af1, bf[1], bf[3]);
        }
        // extras k-step
        uint32_t bex[2];
#pragma unroll
        for (int t = 0; t < 2; t++) {
            float2 cc = cp[wn * 64 + (jp * 2 + t) * 8 + (lane >> 2)];
            bex[t] = k0lane ? h2(cc.x, cc.y) : 0u;
        }
#pragma unroll
        for (int i = 0; i < 2; i++)
#pragma unroll
            for (int t = 0; t < 2; t++)
                mma_f16(acc[i][t], aex[i], bex[t], 0u);

        // epilogue on these 16 columns (x = g+1; tq = x*x-1; arg = x+st)
#pragma unroll
        for (int i = 0; i < 2; i++) {
#pragma unroll
            for (int t = 0; t < 2; t++) {
#pragma unroll
                for (int h = 0; h < 2; h++) {
                    float s2 = sc2[2 * i + h];
#pragma unroll
                    for (int q = 0; q < 2; q++) {
                        float e  = acc[i][t][h * 2 + q];
                        float g  = fmaxf(e, 0.f);
                        float x  = g + 1.0f;
                        float tq = fmaf(x, x, -1.0f);
                        float st;  asm("sqrt.approx.f32 %0, %1;" : "=f"(st) : "f"(tq));
                        float arg = x + st;
                        float lg;  asm("lg2.approx.f32 %0, %1;" : "=f"(lg) : "f"(arg));
                        hs += fmaxf(s2 - lg, 0.f);
                    }
                }
            }
        }
    }

    // ---- reduce + fused finalize ----
#pragma unroll
    for (int s = 16; s > 0; s >>= 1)
        hs += __shfl_xor_sync(0xFFFFFFFFu, hs, s);
    if (lane == 0) ((float*)(smem + OFF_RED))[w] = hs;
    __syncthreads();
    if (w == 0) {
        float v = (lane < 8) ? ((float*)(smem + OFF_RED))[lane] : 0.f;
#pragma unroll
        for (int s = 4; s > 0; s >>= 1)
            v += __shfl_xor_sync(0xFFFFFFFFu, v, s);
        if (lane == 0) {
            atomicAdd(&g_hsum, (double)(v * LN2));
            __threadfence();
            unsigned int ticket = atomicAdd(&g_count, 1u);
            if (ticket == nblocks - 1u) {
                double h = g_hsum;
                out[0] = (float)((h - 0.1 * (double)B) / (double)B);
            }
        }
    }
}

extern "C" void kernel_launch(void* const* d_in, const int* in_sizes, int n_in,
                              void* d_out, int out_size) {
    const float* pred = (const float*)d_in[0];
    const float* tgt  = (const float*)d_in[1];
    const float* all  = (const float*)d_in[2];
    float* out = (float*)d_out;

    int B = in_sizes[0] / 64;
    int C = in_sizes[2] / 64;
    int Bp = ((B + 127) / 128) * 128;
    int Cp = ((C + 127) / 128) * 128;

    cudaFuncSetAttribute(poincare_mma_kernel,
                         cudaFuncAttributeMaxDynamicSharedMemorySize, SMEM_SZ);

    int nthr = ((Bp > Cp) ? Bp : Cp) * 8;
    prep_kernel<<<(nthr + 255) / 256, 256>>>(pred, tgt, all, B, C, Bp, Cp);

    dim3 grid(Cp / BN, Bp / BM);
    unsigned int nblocks = grid.x * grid.y;
    poincare_mma_kernel<<<grid, 256, SMEM_SZ>>>(out, B, C, nblocks);
}

// round 16
// speedup vs baseline: 1.1182x; 1.0952x over previous
#include <cuda_runtime.h>
#include <cuda_fp16.h>
#include <cstdint>

#define MARGIN   0.1f
#define BEPS     1e-5f
#define LN2      0.69314718056f

#define MAXB 4608
#define MAXC 10240

static __device__ double       g_hsum;
static __device__ unsigned int g_count;
static __device__ float4  g_rowp[MAXB];        // (pn*cb, cb, invT, 0)   invT = exp(-(d_corr+MARGIN))
static __device__ float2  g_colp[MAXC];        // (ca, an*ca)  [pad: (0, 3e4)]
static __device__ __half  g_As[MAXB * 64];     // fp16(-2*cb*pred), row-swizzled (128B rows)
static __device__ __half  g_Bs[MAXC * 64];     // fp16(ca*all),     row-swizzled

// ---------------- helpers ----------------
__device__ __forceinline__ uint32_t smem_u32(const void* p) {
    uint32_t a;
    asm("{ .reg .u64 t; cvta.to.shared.u64 t, %1; cvt.u32.u64 %0, t; }" : "=r"(a) : "l"(p));
    return a;
}
__device__ __forceinline__ uint32_t h2(float a, float b) {
    __half2 v = __floats2half2_rn(a, b);
    return *(uint32_t*)&v;
}
__device__ __forceinline__ void ldm_x4(uint32_t* r, uint32_t addr) {
    asm volatile("ldmatrix.sync.aligned.m8n8.x4.shared.b16 {%0,%1,%2,%3}, [%4];"
                 : "=r"(r[0]), "=r"(r[1]), "=r"(r[2]), "=r"(r[3]) : "r"(addr));
}
__device__ __forceinline__ void mma_f16(float* c, const uint32_t* a,
                                        uint32_t b0, uint32_t b1) {
    asm volatile(
        "mma.sync.aligned.m16n8k16.row.col.f32.f16.f16.f32 "
        "{%0,%1,%2,%3}, {%4,%5,%6,%7}, {%8,%9}, {%0,%1,%2,%3};"
        : "+f"(c[0]), "+f"(c[1]), "+f"(c[2]), "+f"(c[3])
        : "r"(a[0]), "r"(a[1]), "r"(a[2]), "r"(a[3]), "r"(b0), "r"(b1));
}
__device__ __forceinline__ void cp_async16(uint32_t smem_addr, const void* gmem) {
    asm volatile("cp.async.cg.shared.global [%0], [%1], 16;"
                 :: "r"(smem_addr), "l"(gmem) : "memory");
}
// r = min(arg*invT, 1); one element of the hinge product
__device__ __forceinline__ float hinge_r(float e, float invT) {
    float g  = fmaxf(e, 0.f);
    float x  = g + 1.0f;
    float tq = fmaf(x, x, -1.0f);
    float st;  asm("sqrt.approx.f32 %0, %1;" : "=f"(st) : "f"(tq));
    float arg = x + st;
    return fminf(arg * invT, 1.0f);
}

// ---------------- prep ----------------
__global__ void prep_kernel(const float* __restrict__ pred,
                            const float* __restrict__ tgt,
                            const float* __restrict__ all,
                            int B, int C, int Bp, int Cp) {
    int gid  = blockIdx.x * blockDim.x + threadIdx.x;
    if (gid == 0) { g_hsum = 0.0; g_count = 0u; }
    int r    = gid >> 3;
    int lane = gid & 7;

    if (r < Cp) {
        char* dst = (char*)g_Bs + (size_t)r * 128;
        uint32_t so = (uint32_t)((lane ^ (r & 7)) << 4);
        if (r < C) {
            float4 a0 = ((const float4*)(all + (size_t)r * 64))[lane * 2];
            float4 a1 = ((const float4*)(all + (size_t)r * 64))[lane * 2 + 1];
            float s = 0.f;
            s = fmaf(a0.x, a0.x, s); s = fmaf(a0.y, a0.y, s);
            s = fmaf(a0.z, a0.z, s); s = fmaf(a0.w, a0.w, s);
            s = fmaf(a1.x, a1.x, s); s = fmaf(a1.y, a1.y, s);
            s = fmaf(a1.z, a1.z, s); s = fmaf(a1.w, a1.w, s);
            s += __shfl_xor_sync(0xFFFFFFFFu, s, 1);
            s += __shfl_xor_sync(0xFFFFFFFFu, s, 2);
            s += __shfl_xor_sync(0xFFFFFFFFu, s, 4);
            float an = fminf(fmaxf(s, 0.f), 1.0f - BEPS);
            float ca = 1.0f / (1.0f - an);
            *(uint4*)(dst + so) = make_uint4(
                h2(ca*a0.x, ca*a0.y), h2(ca*a0.z, ca*a0.w),
                h2(ca*a1.x, ca*a1.y), h2(ca*a1.z, ca*a1.w));
            if (lane == 0) g_colp[r] = make_float2(ca, an * ca);
        } else {
            *(uint4*)(dst + so) = make_uint4(0u, 0u, 0u, 0u);
            if (lane == 0) g_colp[r] = make_float2(0.f, 3e4f);
        }
    }

    if (r < Bp) {
        char* dst = (char*)g_As + (size_t)r * 128;
        uint32_t so = (uint32_t)((lane ^ (r & 7)) << 4);
        if (r < B) {
            float4 p0 = ((const float4*)(pred + (size_t)r * 64))[lane * 2];
            float4 p1 = ((const float4*)(pred + (size_t)r * 64))[lane * 2 + 1];
            float4 t0 = ((const float4*)(tgt  + (size_t)r * 64))[lane * 2];
            float4 t1 = ((const float4*)(tgt  + (size_t)r * 64))[lane * 2 + 1];
            float pn = 0.f, tn = 0.f, sq = 0.f;
            pn = fmaf(p0.x,p0.x,pn); pn = fmaf(p0.y,p0.y,pn); pn = fmaf(p0.z,p0.z,pn); pn = fmaf(p0.w,p0.w,pn);
            pn = fmaf(p1.x,p1.x,pn); pn = fmaf(p1.y,p1.y,pn); pn = fmaf(p1.z,p1.z,pn); pn = fmaf(p1.w,p1.w,pn);
            tn = fmaf(t0.x,t0.x,tn); tn = fmaf(t0.y,t0.y,tn); tn = fmaf(t0.z,t0.z,tn); tn = fmaf(t0.w,t0.w,tn);
            tn = fmaf(t1.x,t1.x,tn); tn = fmaf(t1.y,t1.y,tn); tn = fmaf(t1.z,t1.z,tn); tn = fmaf(t1.w,t1.w,tn);
            float dx;
            dx = p0.x-t0.x; sq = fmaf(dx,dx,sq); dx = p0.y-t0.y; sq = fmaf(dx,dx,sq);
            dx = p0.z-t0.z; sq = fmaf(dx,dx,sq); dx = p0.w-t0.w; sq = fmaf(dx,dx,sq);
            dx = p1.x-t1.x; sq = fmaf(dx,dx,sq); dx = p1.y-t1.y; sq = fmaf(dx,dx,sq);
            dx = p1.z-t1.z; sq = fmaf(dx,dx,sq); dx = p1.w-t1.w; sq = fmaf(dx,dx,sq);
            pn += __shfl_xor_sync(0xFFFFFFFFu, pn, 1);
            pn += __shfl_xor_sync(0xFFFFFFFFu, pn, 2);
            pn += __shfl_xor_sync(0xFFFFFFFFu, pn, 4);
            tn += __shfl_xor_sync(0xFFFFFFFFu, tn, 1);
            tn += __shfl_xor_sync(0xFFFFFFFFu, tn, 2);
            tn += __shfl_xor_sync(0xFFFFFFFFu, tn, 4);
            sq += __shfl_xor_sync(0xFFFFFFFFu, sq, 1);
            sq += __shfl_xor_sync(0xFFFFFFFFu, sq, 2);
            sq += __shfl_xor_sync(0xFFFFFFFFu, sq, 4);
            pn = fminf(fmaxf(pn, 0.f), 1.0f - BEPS);
            tn = fminf(fmaxf(tn, 0.f), 1.0f - BEPS);
            float cb = 2.0f / (1.0f - pn);
            float m2cb = -2.0f * cb;
            *(uint4*)(dst + so) = make_uint4(
                h2(m2cb*p0.x, m2cb*p0.y), h2(m2cb*p0.z, m2cb*p0.w),
                h2(m2cb*p1.x, m2cb*p1.y), h2(m2cb*p1.z, m2cb*p1.w));
            if (lane == 0) {
                float x = 1.0f + 2.0f * sq / ((1.0f - pn) * (1.0f - tn));
                x = fmaxf(x, 1.0f + 1e-7f);
                float d2c = logf(x + sqrtf(x * x - 1.0f));
                float invT = expf(-(d2c + MARGIN));   // arg*invT<1 <=> hinge active
                g_rowp[r] = make_float4(pn * cb, cb, invT, 0.f);
            }
        } else {
            *(uint4*)(dst + so) = make_uint4(0u, 0u, 0u, 0u);
            if (lane == 0) g_rowp[r] = make_float4(0.f, 0.f, 1.0f, 0.f);  // invT=1 -> r=1 -> 0
        }
    }
}

// ---------------- main ----------------
#define BM 128
#define BN 128
#define OFF_A    0
#define OFF_B    16384
#define OFF_CP   32768
#define OFF_RED  33792
#define SMEM_SZ  33856

__global__ __launch_bounds__(256, 3)
void poincare_mma_kernel(float* __restrict__ out, int B, int C, unsigned int nblocks) {
    extern __shared__ char smem[];
    const uint32_t sbase = smem_u32(smem);
    const int tid  = threadIdx.x;
    const int w    = tid >> 5;
    const int lane = tid & 31;
    const int bm   = blockIdx.y * BM;
    const int bn   = blockIdx.x * BN;
    const int wm   = w & 3;
    const int wn   = w >> 2;

    // ---- async tile copy ----
    {
        const char* srcA = (const char*)g_As + (size_t)bm * 128;
        const char* srcB = (const char*)g_Bs + (size_t)bn * 128;
#pragma unroll
        for (int i = 0; i < 4; i++) {
            int idx = tid + i * 256;
            cp_async16(sbase + OFF_A + (idx << 4), srcA + (idx << 4));
            cp_async16(sbase + OFF_B + (idx << 4), srcB + (idx << 4));
        }
        asm volatile("cp.async.commit_group;" ::: "memory");
    }
    if (tid < 128) {
        float2 cpv = g_colp[bn + tid];
        ((float2*)(smem + OFF_CP))[tid] = cpv;
    }
    asm volatile("cp.async.wait_group 0;" ::: "memory");
    __syncthreads();

    // ---- fragment addressing ----
    const int rsel = lane & 15;
    const int csel = lane >> 4;
    const int rowA = wm * 32 + rsel;
    const int swA  = rowA & 7;
    const uint32_t baseA = sbase + OFF_A + (uint32_t)(rowA << 7);
    const int rB   = wn * 64 + rsel;
    const int swB  = rB & 7;
    const uint32_t baseB = sbase + OFF_B + (uint32_t)(rB << 7);

    // ---- row params: invT per row-group + extras A fragment ----
    float invT[4];
    uint32_t aex[2][4];
    {
        const bool k0 = (lane & 3) == 0;
        int rbase = bm + wm * 32 + (lane >> 2);
        float4 r0 = g_rowp[rbase];
        float4 r1 = g_rowp[rbase + 8];
        float4 r2 = g_rowp[rbase + 16];
        float4 r3 = g_rowp[rbase + 24];
        invT[0] = r0.z; invT[1] = r1.z; invT[2] = r2.z; invT[3] = r3.z;
        aex[0][0] = k0 ? h2(r0.x, r0.y) : 0u;
        aex[0][1] = k0 ? h2(r1.x, r1.y) : 0u;
        aex[0][2] = 0u; aex[0][3] = 0u;
        aex[1][0] = k0 ? h2(r2.x, r2.y) : 0u;
        aex[1][1] = k0 ? h2(r3.x, r3.y) : 0u;
        aex[1][2] = 0u; aex[1][3] = 0u;
    }
    const bool k0lane = (lane & 3) == 0;
    const float2* cp = (const float2*)(smem + OFF_CP);

    // lp accumulates lg2 of hinge products (<= 0); hinge_sum = -LN2 * lp
    float lp = 0.f;
#pragma unroll
    for (int jp = 0; jp < 4; jp++) {
        float acc[2][2][4];
#pragma unroll
        for (int i = 0; i < 2; i++)
#pragma unroll
            for (int t = 0; t < 2; t++)
#pragma unroll
                for (int q = 0; q < 4; q++) acc[i][t][q] = 0.f;

#pragma unroll
        for (int s = 0; s < 4; s++) {
            uint32_t af0[4], af1[4], bf[4];
            uint32_t koff = (uint32_t)((2 * s + csel));
            ldm_x4(af0, baseA + (uint32_t)(((koff ^ swA) << 4)));
            ldm_x4(af1, baseA + (uint32_t)(16 * 128) + (uint32_t)(((koff ^ swA) << 4)));
            ldm_x4(bf,  baseB + (uint32_t)(jp * 16 * 128) + (uint32_t)(((koff ^ swB) << 4)));
            mma_f16(acc[0][0], af0, bf[0], bf[2]);
            mma_f16(acc[0][1], af0, bf[1], bf[3]);
            mma_f16(acc[1][0], af1, bf[0], bf[2]);
            mma_f16(acc[1][1], af1, bf[1], bf[3]);
        }
        // extras k-step: acc = cbca*(pn+an-2dot)
        uint32_t bex[2];
#pragma unroll
        for (int t = 0; t < 2; t++) {
            float2 cc = cp[wn * 64 + (jp * 2 + t) * 8 + (lane >> 2)];
            bex[t] = k0lane ? h2(cc.x, cc.y) : 0u;
        }
#pragma unroll
        for (int i = 0; i < 2; i++)
#pragma unroll
            for (int t = 0; t < 2; t++)
                mma_f16(acc[i][t], aex[i], bex[t], 0u);

        // epilogue: 8 elements -> 1 lg2 (product of clamped ratios)
#pragma unroll
        for (int i = 0; i < 2; i++) {
            float r0 = hinge_r(acc[i][0][0], invT[2 * i]);
            float r1 = hinge_r(acc[i][0][1], invT[2 * i]);
            float r2 = hinge_r(acc[i][0][2], invT[2 * i + 1]);
            float r3 = hinge_r(acc[i][0][3], invT[2 * i + 1]);
            float r4 = hinge_r(acc[i][1][0], invT[2 * i]);
            float r5 = hinge_r(acc[i][1][1], invT[2 * i]);
            float r6 = hinge_r(acc[i][1][2], invT[2 * i + 1]);
            float r7 = hinge_r(acc[i][1][3], invT[2 * i + 1]);
            float p01 = r0 * r1, p23 = r2 * r3, p45 = r4 * r5, p67 = r6 * r7;
            float pa = p01 * p23, pb = p45 * p67;
            float P  = pa * pb;
            float lg;  asm("lg2.approx.f32 %0, %1;" : "=f"(lg) : "f"(P));
            lp += lg;
        }
    }

    // ---- reduce + fused finalize (hinge = -LN2 * lp) ----
    float hs = lp;
#pragma unroll
    for (int s = 16; s > 0; s >>= 1)
        hs += __shfl_xor_sync(0xFFFFFFFFu, hs, s);
    if (lane == 0) ((float*)(smem + OFF_RED))[w] = hs;
    __syncthreads();
    if (w == 0) {
        float v = (lane < 8) ? ((float*)(smem + OFF_RED))[lane] : 0.f;
#pragma unroll
        for (int s = 4; s > 0; s >>= 1)
            v += __shfl_xor_sync(0xFFFFFFFFu, v, s);
        if (lane == 0) {
            atomicAdd(&g_hsum, (double)(-LN2 * v));
            __threadfence();
            unsigned int ticket = atomicAdd(&g_count, 1u);
            if (ticket == nblocks - 1u) {
                double h = g_hsum;
                out[0] = (float)((h - 0.1 * (double)B) / (double)B);
            }
        }
    }
}

extern "C" void kernel_launch(void* const* d_in, const int* in_sizes, int n_in,
                              void* d_out, int out_size) {
    const float* pred = (const float*)d_in[0];
    const float* tgt  = (const float*)d_in[1];
    const float* all  = (const float*)d_in[2];
    float* out = (float*)d_out;

    int B = in_sizes[0] / 64;
    int C = in_sizes[2] / 64;
    int Bp = ((B + 127) / 128) * 128;
    int Cp = ((C + 127) / 128) * 128;

    cudaFuncSetAttribute(poincare_mma_kernel,
                         cudaFuncAttributeMaxDynamicSharedMemorySize, SMEM_SZ);

    int nthr = ((Bp > Cp) ? Bp : Cp) * 8;
    prep_kernel<<<(nthr + 255) / 256, 256>>>(pred, tgt, all, B, C, Bp, Cp);

    dim3 grid(Cp / BN, Bp / BM);
    unsigned int nblocks = grid.x * grid.y;
    poincare_mma_kernel<<<grid, 256, SMEM_SZ>>>(out, B, C, nblocks);
}